// round 2
// baseline (speedup 1.0000x reference)
#include <cuda_runtime.h>
#include <math.h>

#define BSZ 512
#define DDIM 1024
#define HDIM 4096
#define TAUV 20
#define TT 21
#define TOPKV 100

// -------- scratch (device globals; no allocation allowed) --------
__device__ float g_Xt[(size_t)BSZ * TT * DDIM];        // [b][t][d]   44 MB
__device__ float g_Zp[(size_t)TT * BSZ * HDIM];        // [t][b][h]  176 MB
__device__ float g_Zt[(size_t)BSZ * HDIM];             // [b][h]       8 MB
__device__ double g_acc[8];                            // reductions

// acc slots: 0=mseXt 1=mseZt 2=indep 3=absBs 4=absM 5=absZt

__global__ void k_zero_acc() {
    if (threadIdx.x < 8) g_acc[threadIdx.x] = 0.0;
}

// Xp (b,d,t) -> g_Xt (b,t,d)
__global__ void k_transpose(const float* __restrict__ Xp) {
    int idx = blockIdx.x * blockDim.x + threadIdx.x;
    const int total = BSZ * DDIM * TT;
    if (idx >= total) return;
    int b = idx / (DDIM * TT);
    int r = idx - b * (DDIM * TT);
    int d = r / TT;
    int t = r - d * TT;
    g_Xt[(size_t)b * TT * DDIM + (size_t)t * DDIM + d] = Xp[idx];
}

// ---------------------------------------------------------------------------
// Generic NN SGEMM: C[m,n] = sum_k A[m*lda+k] * Bm[k*ldb+n]
// 128x128 tile, BK=8, 256 threads, 8x8 per thread, register-prefetch
// double buffering (next global tile loaded while smem tile is consumed).
// mode 0: write result to g_Zp with m=(b*21+t) scatter  (GEMM1: Zp)
// mode 1: fused mse vs Xp[:, :, 20]  (recons: loss_mse_Xt)
// ---------------------------------------------------------------------------
__global__ __launch_bounds__(256, 1) void k_gemm_nn(
    const float* __restrict__ A, const float* __restrict__ Bm,
    int Kdim, int lda, int ldb, int mode, const float* __restrict__ Xp)
{
    __shared__ float As[8][128];
    __shared__ float Bsh[8][128];
    const int tid = threadIdx.x;
    const int tx = tid & 15, ty = tid >> 4;
    const int m0 = blockIdx.x * 128, n0 = blockIdx.y * 128;

    float acc[8][8];
#pragma unroll
    for (int i = 0; i < 8; i++)
#pragma unroll
        for (int j = 0; j < 8; j++) acc[i][j] = 0.f;

    const int arow = tid >> 1, acol = (tid & 1) << 2;
    const int brow = tid >> 5, bcol = (tid & 31) << 2;
    const float* Aptr = A + (size_t)(m0 + arow) * lda + acol;
    const float* Bptr = Bm + (size_t)brow * ldb + n0 + bcol;

    float4 av = *(const float4*)(Aptr);
    float4 bv = *(const float4*)(Bptr);

    for (int k0 = 0; k0 < Kdim; k0 += 8) {
        As[acol + 0][arow] = av.x;
        As[acol + 1][arow] = av.y;
        As[acol + 2][arow] = av.z;
        As[acol + 3][arow] = av.w;
        *(float4*)&Bsh[brow][bcol] = bv;
        __syncthreads();
        if (k0 + 8 < Kdim) {          // prefetch next tile while computing
            av = *(const float4*)(Aptr + k0 + 8);
            bv = *(const float4*)(Bptr + (size_t)(k0 + 8) * ldb);
        }
#pragma unroll
        for (int kk = 0; kk < 8; kk++) {
            float a[8], b[8];
            *(float4*)(a)     = *(const float4*)&As[kk][ty * 8];
            *(float4*)(a + 4) = *(const float4*)&As[kk][ty * 8 + 4];
            *(float4*)(b)     = *(const float4*)&Bsh[kk][tx * 8];
            *(float4*)(b + 4) = *(const float4*)&Bsh[kk][tx * 8 + 4];
#pragma unroll
            for (int i = 0; i < 8; i++)
#pragma unroll
                for (int j = 0; j < 8; j++) acc[i][j] += a[i] * b[j];
        }
        __syncthreads();
    }

    if (mode == 0) {
#pragma unroll
        for (int i = 0; i < 8; i++) {
            int m = m0 + ty * 8 + i;
            int b = m / TT, t = m - b * TT;
            float* dst = g_Zp + (size_t)t * BSZ * HDIM + (size_t)b * HDIM + n0 + tx * 8;
            *(float4*)(dst)     = *(float4*)&acc[i][0];
            *(float4*)(dst + 4) = *(float4*)&acc[i][4];
        }
    } else {
        double s = 0.0;
#pragma unroll
        for (int i = 0; i < 8; i++) {
            int m = m0 + ty * 8 + i;  // = b
#pragma unroll
            for (int j = 0; j < 8; j++) {
                int n = n0 + tx * 8 + j;  // = d
                float x = Xp[(size_t)m * DDIM * TT + (size_t)n * TT + (TT - 1)];
                float diff = acc[i][j] - x;
                s += (double)diff * (double)diff;
            }
        }
        __shared__ double red[256];
        red[tid] = s;
        __syncthreads();
        for (int off = 128; off > 0; off >>= 1) {
            if (tid < off) red[tid] += red[tid + off];
            __syncthreads();
        }
        if (tid == 0) atomicAdd(&g_acc[0], red[0]);
    }
}

// ---------------------------------------------------------------------------
// Big GEMM: Zt[b,h] = sum_{l<20} sum_d Bs[l,h,d]*Zp[b,d,19-l]
//                    + sum_d tril(M,1)[h,d]*Zp[b,d,20]
// NT gemm; (l, k0) flattened into one loop so register prefetch crosses
// slab boundaries. tril mask + fused |Bs|/|tril(M,1)| sums applied to the
// CURRENT register tile at consume time (prefetched tile stays raw).
// ---------------------------------------------------------------------------
__global__ __launch_bounds__(256, 1) void k_gemm2(
    const float* __restrict__ Bs, const float* __restrict__ Mmat)
{
    __shared__ float As[8][128];
    __shared__ float Wsh[8][128];
    const int tid = threadIdx.x;
    const int tx = tid & 15, ty = tid >> 4;
    const int m0 = blockIdx.x * 128, n0 = blockIdx.y * 128;

    float acc[8][8];
#pragma unroll
    for (int i = 0; i < 8; i++)
#pragma unroll
        for (int j = 0; j < 8; j++) acc[i][j] = 0.f;

    const int arow = tid >> 1, acol = (tid & 1) << 2;
    const int wrow = tid >> 1, wcol = (tid & 1) << 2;
    const int hrow = n0 + wrow;
    const bool doAbs = (blockIdx.x == 0);
    double accBs = 0.0, accM = 0.0;

    const int NIT = (TAUV + 1) * (HDIM / 8);   // 21 * 512 = 10752

    auto loadA = [&](int i) -> float4 {
        int l = i >> 9;                         // HDIM/8 = 512 iters per slab
        int kk0 = (i & 511) << 3;
        int tsel = (l < TAUV) ? (TAUV - 1 - l) : TAUV;
        const float* p = g_Zp + (size_t)tsel * BSZ * HDIM
                       + (size_t)(m0 + arow) * HDIM + kk0 + acol;
        return *(const float4*)p;
    };
    auto loadW = [&](int i) -> float4 {
        int l = i >> 9;
        int kk0 = (i & 511) << 3;
        const float* base = (l < TAUV) ? (Bs + (size_t)l * HDIM * HDIM) : Mmat;
        return *(const float4*)(base + (size_t)hrow * HDIM + kk0 + wcol);
    };

    float4 av = loadA(0);
    float4 wv = loadW(0);

    for (int i = 0; i < NIT; i++) {
        const int l = i >> 9;
        if (l == TAUV) {  // tril(M, k=1): keep d <= h+1
            int d0 = ((i & 511) << 3) + wcol;
            if (d0 + 0 > hrow + 1) wv.x = 0.f;
            if (d0 + 1 > hrow + 1) wv.y = 0.f;
            if (d0 + 2 > hrow + 1) wv.z = 0.f;
            if (d0 + 3 > hrow + 1) wv.w = 0.f;
        }
        if (doAbs) {
            float sab = fabsf(wv.x) + fabsf(wv.y) + fabsf(wv.z) + fabsf(wv.w);
            if (l < TAUV) accBs += (double)sab; else accM += (double)sab;
        }
        As[acol + 0][arow] = av.x;
        As[acol + 1][arow] = av.y;
        As[acol + 2][arow] = av.z;
        As[acol + 3][arow] = av.w;
        Wsh[wcol + 0][wrow] = wv.x;
        Wsh[wcol + 1][wrow] = wv.y;
        Wsh[wcol + 2][wrow] = wv.z;
        Wsh[wcol + 3][wrow] = wv.w;
        __syncthreads();
        if (i + 1 < NIT) {            // prefetch next tile while computing
            av = loadA(i + 1);
            wv = loadW(i + 1);
        }
#pragma unroll
        for (int kk = 0; kk < 8; kk++) {
            float a[8], b[8];
            *(float4*)(a)     = *(const float4*)&As[kk][ty * 8];
            *(float4*)(a + 4) = *(const float4*)&As[kk][ty * 8 + 4];
            *(float4*)(b)     = *(const float4*)&Wsh[kk][tx * 8];
            *(float4*)(b + 4) = *(const float4*)&Wsh[kk][tx * 8 + 4];
#pragma unroll
            for (int ii = 0; ii < 8; ii++)
#pragma unroll
                for (int jj = 0; jj < 8; jj++) acc[ii][jj] += a[ii] * b[jj];
        }
        __syncthreads();
    }

#pragma unroll
    for (int i = 0; i < 8; i++) {
        float* dst = g_Zt + (size_t)(m0 + ty * 8 + i) * HDIM + n0 + tx * 8;
        *(float4*)(dst)     = *(float4*)&acc[i][0];
        *(float4*)(dst + 4) = *(float4*)&acc[i][4];
    }

    if (doAbs) {
        __shared__ double redB[256];
        __shared__ double redM[256];
        redB[tid] = accBs;
        redM[tid] = accM;
        __syncthreads();
        for (int off = 128; off > 0; off >>= 1) {
            if (tid < off) { redB[tid] += redB[tid + off]; redM[tid] += redM[tid + off]; }
            __syncthreads();
        }
        if (tid == 0) {
            atomicAdd(&g_acc[3], redB[0]);
            atomicAdd(&g_acc[4], redM[0]);
        }
    }
}

// ---------------------------------------------------------------------------
// Per-row top-100 by |Zt| via binary search on the float bit pattern
// (nonnegative floats are order-isomorphic to their uint32 bits), then the
// three Zt losses.
// ---------------------------------------------------------------------------
__global__ __launch_bounds__(256, 1) void k_topk_losses() {
    __shared__ unsigned sabs[HDIM];  // 16 KB
    __shared__ int scnt[256];
    __shared__ double sred[256];
    const int b = blockIdx.x;
    const int tid = threadIdx.x;
    const float* zrow = g_Zt + (size_t)b * HDIM;
    const float* zlrow = g_Zp + (size_t)TAUV * BSZ * HDIM + (size_t)b * HDIM;

    for (int h = tid; h < HDIM; h += 256)
        sabs[h] = __float_as_uint(fabsf(zrow[h]));
    __syncthreads();

    // largest x with count(|z| >= x) >= TOPK  ->  x = bits of the 100th largest
    unsigned lo = 0u, hi = 0x7f800000u;
    while (lo < hi) {
        unsigned mid = lo + (hi - lo + 1) / 2;
        int c = 0;
        for (int h = tid; h < HDIM; h += 256) c += (sabs[h] >= mid) ? 1 : 0;
        scnt[tid] = c;
        __syncthreads();
        for (int off = 128; off > 0; off >>= 1) {
            if (tid < off) scnt[tid] += scnt[tid + off];
            __syncthreads();
        }
        int cnt = scnt[0];
        __syncthreads();
        if (cnt >= TOPKV) lo = mid; else hi = mid - 1;
    }
    const unsigned thr = lo;

    double s1 = 0.0, s2 = 0.0, s3 = 0.0;
    for (int h = tid; h < HDIM; h += 256) {
        float z = zrow[h];
        float zl = zlrow[h];
        float zm = (sabs[h] >= thr) ? z : 0.f;
        float d1 = zm - zl;
        s1 += (double)d1 * (double)d1;
        s2 += fabs((double)zl - (double)zm);
        s3 += fabs((double)zm);
    }
    sred[tid] = s1;
    __syncthreads();
    for (int off = 128; off > 0; off >>= 1) {
        if (tid < off) sred[tid] += sred[tid + off];
        __syncthreads();
    }
    if (tid == 0) atomicAdd(&g_acc[1], sred[0]);
    __syncthreads();
    sred[tid] = s2;
    __syncthreads();
    for (int off = 128; off > 0; off >>= 1) {
        if (tid < off) sred[tid] += sred[tid + off];
        __syncthreads();
    }
    if (tid == 0) atomicAdd(&g_acc[2], sred[0]);
    __syncthreads();
    sred[tid] = s3;
    __syncthreads();
    for (int off = 128; off > 0; off >>= 1) {
        if (tid < off) sred[tid] += sred[tid + off];
        __syncthreads();
    }
    if (tid == 0) atomicAdd(&g_acc[5], sred[0]);
}

__global__ void k_finalize(float* out) {
    if (threadIdx.x == 0) {
        out[0] = (float)(g_acc[0] / ((double)BSZ * DDIM));
        out[1] = (float)(g_acc[1] / ((double)BSZ * HDIM));
        out[2] = (float)(g_acc[2] / ((double)BSZ * HDIM));
        out[3] = (float)(g_acc[3] / ((double)HDIM * HDIM));
        out[4] = (float)(g_acc[4] / ((double)HDIM * HDIM));
        out[5] = (float)(g_acc[5] / ((double)BSZ * HDIM));
    }
}

extern "C" void kernel_launch(void* const* d_in, const int* in_sizes, int n_in,
                              void* d_out, int out_size) {
    const float* Xp    = (const float*)d_in[0];  // (512,1024,21)
    const float* F_enc = (const float*)d_in[1];  // (1024,4096)
    const float* F_dec = (const float*)d_in[2];  // (4096,1024)
    const float* Bs    = (const float*)d_in[3];  // (20,4096,4096)
    const float* Mm    = (const float*)d_in[4];  // (4096,4096)
    float* out = (float*)d_out;                  // 6 floats

    void* pXt = nullptr;
    void* pZp = nullptr;
    cudaGetSymbolAddress(&pXt, g_Xt);
    cudaGetSymbolAddress(&pZp, g_Zp);
    const float* Xt_ptr = (const float*)pXt;
    const float* Zlast_ptr = (const float*)pZp + (size_t)TAUV * BSZ * HDIM;

    k_zero_acc<<<1, 32>>>();

    {
        const int total = BSZ * DDIM * TT;
        k_transpose<<<(total + 255) / 256, 256>>>(Xp);
    }

    // GEMM1: Zp[(b,t), h] = Xt[(b,t), d] @ F_enc[d, h]
    // M = 512*21 = 10752 (84 tiles), N = 4096 (32 tiles), K = 1024
    k_gemm_nn<<<dim3(84, 32), 256>>>(Xt_ptr, F_enc, DDIM, DDIM, HDIM, 0, nullptr);

    // Big GEMM + fused |Bs|, |tril(M,1)| sums
    k_gemm2<<<dim3(4, 32), 256>>>(Bs, Mm);

    // recons GEMM fused with loss_mse_Xt:
    // M = 512 (4 tiles), N = 1024 (8 tiles), K = 4096
    k_gemm_nn<<<dim3(4, 8), 256>>>(Zlast_ptr, F_dec, HDIM, HDIM, DDIM, 1, Xp);

    // top-k + Zt losses
    k_topk_losses<<<BSZ, 256>>>();

    k_finalize<<<1, 32>>>(out);
}

// round 8
// speedup vs baseline: 1.8412x; 1.8412x over previous
#include <cuda_runtime.h>
#include <cuda_bf16.h>
#include <math.h>
#include <stdint.h>

#define BSZ 512
#define DDIM 1024
#define HDIM 4096
#define TAUV 20
#define TT 21
#define TOPKV 100

#define ROWB 80  // smem row pitch bytes: 32 bf16 (64B) + 16B pad -> ldmatrix conflict-free
#define STAGE_BYTES (4 * 128 * ROWB)          // A_hi, A_lo, B_hi, B_lo  = 40960
#define SMEM_DYN_BYTES (2 * STAGE_BYTES)      // 81920

// -------- scratch (device globals; no allocation allowed) --------
__device__ float g_Xt[(size_t)BSZ * TT * DDIM];        // [b][t][d]
__device__ float g_Fet[(size_t)HDIM * DDIM];           // F_enc^T [h][d]
__device__ float g_Zp[(size_t)TT * BSZ * HDIM];        // [t][b][h]
__device__ float g_Zt[(size_t)BSZ * HDIM];             // [b][h]
__device__ double g_acc[8];
// acc slots: 0=mseXt 1=mseZt 2=indep 3=absBs 4=absM 5=absZt

// ======================= helpers =======================
__device__ __forceinline__ uint32_t smem_u32(const void* p) {
    uint32_t a;
    asm("{ .reg .u64 t; cvta.to.shared.u64 t, %1; cvt.u32.u64 %0, t; }" : "=r"(a) : "l"(p));
    return a;
}
__device__ __forceinline__ void ldsm_x4(uint32_t* r, uint32_t addr) {
    asm volatile("ldmatrix.sync.aligned.m8n8.x4.shared.b16 {%0,%1,%2,%3}, [%4];"
                 : "=r"(r[0]), "=r"(r[1]), "=r"(r[2]), "=r"(r[3]) : "r"(addr));
}
__device__ __forceinline__ void mma16816(float* c, const uint32_t* a, uint32_t b0, uint32_t b1) {
    asm volatile(
        "mma.sync.aligned.m16n8k16.row.col.f32.bf16.bf16.f32 "
        "{%0,%1,%2,%3}, {%4,%5,%6,%7}, {%8,%9}, {%0,%1,%2,%3};"
        : "+f"(c[0]), "+f"(c[1]), "+f"(c[2]), "+f"(c[3])
        : "r"(a[0]), "r"(a[1]), "r"(a[2]), "r"(a[3]), "r"(b0), "r"(b1));
}

// float4 -> bf16 hi (8B) + bf16 lo residual (8B) at flat smem offset
__device__ __forceinline__ void store_hi_lo(char* th, char* tl, uint32_t off, float4 v) {
    __nv_bfloat16 h0 = __float2bfloat16(v.x);
    __nv_bfloat16 h1 = __float2bfloat16(v.y);
    __nv_bfloat16 h2 = __float2bfloat16(v.z);
    __nv_bfloat16 h3 = __float2bfloat16(v.w);
    __nv_bfloat16 l0 = __float2bfloat16(v.x - __bfloat162float(h0));
    __nv_bfloat16 l1 = __float2bfloat16(v.y - __bfloat162float(h1));
    __nv_bfloat16 l2 = __float2bfloat16(v.z - __bfloat162float(h2));
    __nv_bfloat16 l3 = __float2bfloat16(v.w - __bfloat162float(h3));
    uint2 hv, lv;
    hv.x = ((uint32_t)__bfloat16_as_ushort(h1) << 16) | __bfloat16_as_ushort(h0);
    hv.y = ((uint32_t)__bfloat16_as_ushort(h3) << 16) | __bfloat16_as_ushort(h2);
    lv.x = ((uint32_t)__bfloat16_as_ushort(l1) << 16) | __bfloat16_as_ushort(l0);
    lv.y = ((uint32_t)__bfloat16_as_ushort(l3) << 16) | __bfloat16_as_ushort(l2);
    *(uint2*)(th + off) = hv;
    *(uint2*)(tl + off) = lv;
}

// one Kc=32 chunk of 3-term HMMA from smem stage; acc[2][8][4]
__device__ __forceinline__ void compute_chunk(float acc[2][8][4],
                                              uint32_t sAh, uint32_t sAl,
                                              uint32_t sBh, uint32_t sBl,
                                              int lane, int wm, int wn) {
#pragma unroll
    for (int ks = 0; ks < 2; ks++) {
        const uint32_t k0b = ks * 32;  // 16 elems = 32 bytes
        // A fragments: 2 m16 tiles; lanes 0-15 rows, 16-31 rows +8-col offset
        uint32_t aoff = (uint32_t)(wm * 32 + (lane & 15)) * ROWB + k0b + ((lane >> 4) & 1) * 16;
        uint32_t aH[2][4], aL[2][4];
        ldsm_x4(aH[0], sAh + aoff);
        ldsm_x4(aH[1], sAh + aoff + 16 * ROWB);
        ldsm_x4(aL[0], sAl + aoff);
        ldsm_x4(aL[1], sAl + aoff + 16 * ROWB);
        // B fragments: 4 x (n16 x k16) loads; lanes: 0-7 (n0,k0) 8-15 (n0,k8) 16-23 (n1,k0) 24-31 (n1,k8)
        uint32_t bH[4][4], bL[4][4];
        uint32_t boff = (uint32_t)(wn * 64 + 8 * ((lane >> 4) & 1) + (lane & 7)) * ROWB
                      + k0b + 16 * ((lane >> 3) & 1);
#pragma unroll
        for (int np = 0; np < 4; np++) {
            ldsm_x4(bH[np], sBh + boff + np * 16 * ROWB);
            ldsm_x4(bL[np], sBl + boff + np * 16 * ROWB);
        }
#pragma unroll
        for (int mt = 0; mt < 2; mt++)
#pragma unroll
            for (int np = 0; np < 4; np++)
#pragma unroll
                for (int sub = 0; sub < 2; sub++) {
                    float* c = acc[mt][np * 2 + sub];
                    mma16816(c, aH[mt], bH[np][sub * 2], bH[np][sub * 2 + 1]);
                    mma16816(c, aH[mt], bL[np][sub * 2], bL[np][sub * 2 + 1]);
                    mma16816(c, aL[mt], bH[np][sub * 2], bH[np][sub * 2 + 1]);
                }
    }
}

__global__ void k_zero_acc() {
    if (threadIdx.x < 8) g_acc[threadIdx.x] = 0.0;
}

// Xp (b,d,t) -> g_Xt (b,t,d)
__global__ void k_transpose(const float* __restrict__ Xp) {
    int idx = blockIdx.x * blockDim.x + threadIdx.x;
    const int total = BSZ * DDIM * TT;
    if (idx >= total) return;
    int b = idx / (DDIM * TT);
    int r = idx - b * (DDIM * TT);
    int d = r / TT;
    int t = r - d * TT;
    g_Xt[(size_t)b * TT * DDIM + (size_t)t * DDIM + d] = Xp[idx];
}

// F_enc (d,h) -> g_Fet (h,d)
__global__ void k_transpose_fenc(const float* __restrict__ Fe) {
    __shared__ float tile[32][33];
    int d0 = blockIdx.x * 32, h0 = blockIdx.y * 32;
    int tx = threadIdx.x, ty = threadIdx.y;
    for (int r = ty; r < 32; r += 8)
        tile[r][tx] = Fe[(size_t)(d0 + r) * HDIM + h0 + tx];
    __syncthreads();
    for (int r = ty; r < 32; r += 8)
        g_Fet[(size_t)(h0 + r) * DDIM + d0 + tx] = tile[tx][r];
}

// ---------------------------------------------------------------------------
// HMMA GEMM1: Zp[(b,t), h] = Xt[(b,t), :] . Fet[h, :]  (K = 1024)
// grid (84, 32), 256 threads, CTA tile 128x128, Kc=32, 2-stage smem + reg prefetch
// ---------------------------------------------------------------------------
__global__ __launch_bounds__(256, 1) void k_gemm1_hmma() {
    extern __shared__ char dsm[];
    const uint32_t sbase = smem_u32(dsm);
    const int tid = threadIdx.x;
    const int lane = tid & 31, w = tid >> 5;
    const int wm = w & 3, wn = w >> 2;
    const int m0 = blockIdx.x * 128, n0 = blockIdx.y * 128;

    float acc[2][8][4];
#pragma unroll
    for (int a = 0; a < 2; a++)
#pragma unroll
        for (int b = 0; b < 8; b++)
#pragma unroll
            for (int c = 0; c < 4; c++) acc[a][b][c] = 0.f;

    const int NIT = DDIM / 32;  // 32
    float4 pa[4], pb[4];
#pragma unroll
    for (int j = 0; j < 4; j++) {
        int fid = tid + j * 256, row = fid >> 3, c4 = fid & 7;
        pa[j] = *(const float4*)(g_Xt + (size_t)(m0 + row) * DDIM + c4 * 4);
        pb[j] = *(const float4*)(g_Fet + (size_t)(n0 + row) * DDIM + c4 * 4);
    }

    for (int i = 0; i < NIT; i++) {
        const int s = i & 1;
        char* st = dsm + s * STAGE_BYTES;
        char* sAh = st;
        char* sAl = st + 10240;
        char* sBh = st + 20480;
        char* sBl = st + 30720;
#pragma unroll
        for (int j = 0; j < 4; j++) {
            int fid = tid + j * 256, row = fid >> 3, c4 = fid & 7;
            store_hi_lo(sAh, sAl, row * ROWB + c4 * 8, pa[j]);
            store_hi_lo(sBh, sBl, row * ROWB + c4 * 8, pb[j]);
        }
        __syncthreads();
        if (i + 1 < NIT) {
            int kg = (i + 1) * 32;
#pragma unroll
            for (int j = 0; j < 4; j++) {
                int fid = tid + j * 256, row = fid >> 3, c4 = fid & 7;
                pa[j] = *(const float4*)(g_Xt + (size_t)(m0 + row) * DDIM + kg + c4 * 4);
                pb[j] = *(const float4*)(g_Fet + (size_t)(n0 + row) * DDIM + kg + c4 * 4);
            }
        }
        uint32_t u = sbase + s * STAGE_BYTES;
        compute_chunk(acc, u, u + 10240, u + 20480, u + 30720, lane, wm, wn);
        __syncthreads();
    }

    // epilogue: scatter m=(b*21+t) rows into g_Zp[t][b][h]
#pragma unroll
    for (int mt = 0; mt < 2; mt++) {
        int r0 = m0 + wm * 32 + mt * 16 + (lane >> 2);
        int b0i = r0 / TT, t0i = r0 - b0i * TT;
        int r1 = r0 + 8;
        int b1i = r1 / TT, t1i = r1 - b1i * TT;
        float* d0p = g_Zp + (size_t)t0i * BSZ * HDIM + (size_t)b0i * HDIM;
        float* d1p = g_Zp + (size_t)t1i * BSZ * HDIM + (size_t)b1i * HDIM;
#pragma unroll
        for (int nt = 0; nt < 8; nt++) {
            int col = n0 + wn * 64 + nt * 8 + (lane & 3) * 2;
            *(float2*)(d0p + col) = make_float2(acc[mt][nt][0], acc[mt][nt][1]);
            *(float2*)(d1p + col) = make_float2(acc[mt][nt][2], acc[mt][nt][3]);
        }
    }
}

// ---------------------------------------------------------------------------
// HMMA big GEMM: Zt[b,h] = sum_{l<20} Bs[l,h,:].Zp[19-l][b,:] + tril(M,1)[h,:].Zp[20][b,:]
// grid (4, 32). Fused |Bs| / |tril M| sums on blockIdx.x==0 (each W element
// loaded exactly once across those CTAs). tril mask applied at store time.
// ---------------------------------------------------------------------------
__global__ __launch_bounds__(256, 1) void k_gemm2_hmma(
    const float* __restrict__ Bs, const float* __restrict__ Mmat)
{
    extern __shared__ char dsm[];
    const uint32_t sbase = smem_u32(dsm);
    const int tid = threadIdx.x;
    const int lane = tid & 31, w = tid >> 5;
    const int wm = w & 3, wn = w >> 2;
    const int m0 = blockIdx.x * 128, n0 = blockIdx.y * 128;
    const bool doAbs = (blockIdx.x == 0);
    double accBs = 0.0, accM = 0.0;

    float acc[2][8][4];
#pragma unroll
    for (int a = 0; a < 2; a++)
#pragma unroll
        for (int b = 0; b < 8; b++)
#pragma unroll
            for (int c = 0; c < 4; c++) acc[a][b][c] = 0.f;

    const int CPS = HDIM / 32;          // 128 chunks per l-slab
    const int NIT = (TAUV + 1) * CPS;   // 2688

    float4 pa[4], pb[4];
    {   // prefetch chunk 0 (l=0 -> tsel=19, Wbase=Bs[0])
        const float* Abase = g_Zp + (size_t)(TAUV - 1) * BSZ * HDIM;
        const float* Wbase = Bs;
#pragma unroll
        for (int j = 0; j < 4; j++) {
            int fid = tid + j * 256, row = fid >> 3, c4 = fid & 7;
            pa[j] = *(const float4*)(Abase + (size_t)(m0 + row) * HDIM + c4 * 4);
            pb[j] = *(const float4*)(Wbase + (size_t)(n0 + row) * HDIM + c4 * 4);
        }
    }

    for (int i = 0; i < NIT; i++) {
        const int s = i & 1;
        const int l = i >> 7;               // i / 128
        const int kglob = (i & 127) << 5;   // (i % 128) * 32
        char* st = dsm + s * STAGE_BYTES;
        char* sAh = st;
        char* sAl = st + 10240;
        char* sBh = st + 20480;
        char* sBl = st + 30720;
#pragma unroll
        for (int j = 0; j < 4; j++) {
            int fid = tid + j * 256, row = fid >> 3, c4 = fid & 7;
            store_hi_lo(sAh, sAl, row * ROWB + c4 * 8, pa[j]);
            float4 wv = pb[j];
            int h = n0 + row;
            int d0 = kglob + c4 * 4;
            if (l == TAUV) {  // tril(M, k=1): keep d <= h+1
                if (d0 + 0 > h + 1) wv.x = 0.f;
                if (d0 + 1 > h + 1) wv.y = 0.f;
                if (d0 + 2 > h + 1) wv.z = 0.f;
                if (d0 + 3 > h + 1) wv.w = 0.f;
            }
            if (doAbs) {
                float sab = fabsf(wv.x) + fabsf(wv.y) + fabsf(wv.z) + fabsf(wv.w);
                if (l < TAUV) accBs += (double)sab; else accM += (double)sab;
            }
            store_hi_lo(sBh, sBl, row * ROWB + c4 * 8, wv);
        }
        __syncthreads();
        if (i + 1 < NIT) {
            int ci = i + 1;
            int ln = ci >> 7;
            int kg = (ci & 127) << 5;
            int tsel = (ln < TAUV) ? (TAUV - 1 - ln) : TAUV;
            const float* Abase = g_Zp + (size_t)tsel * BSZ * HDIM;
            const float* Wbase = (ln < TAUV) ? (Bs + (size_t)ln * HDIM * HDIM) : Mmat;
#pragma unroll
            for (int j = 0; j < 4; j++) {
                int fid = tid + j * 256, row = fid >> 3, c4 = fid & 7;
                pa[j] = *(const float4*)(Abase + (size_t)(m0 + row) * HDIM + kg + c4 * 4);
                pb[j] = *(const float4*)(Wbase + (size_t)(n0 + row) * HDIM + kg + c4 * 4);
            }
        }
        uint32_t u = sbase + s * STAGE_BYTES;
        compute_chunk(acc, u, u + 10240, u + 20480, u + 30720, lane, wm, wn);
        __syncthreads();
    }

    // epilogue: Zt[b][h]
#pragma unroll
    for (int mt = 0; mt < 2; mt++) {
        int r0 = m0 + wm * 32 + mt * 16 + (lane >> 2);
#pragma unroll
        for (int nt = 0; nt < 8; nt++) {
            int col = n0 + wn * 64 + nt * 8 + (lane & 3) * 2;
            *(float2*)(g_Zt + (size_t)r0 * HDIM + col) = make_float2(acc[mt][nt][0], acc[mt][nt][1]);
            *(float2*)(g_Zt + (size_t)(r0 + 8) * HDIM + col) = make_float2(acc[mt][nt][2], acc[mt][nt][3]);
        }
    }

    if (doAbs) {
        __shared__ double redB[256];
        __shared__ double redM[256];
        redB[tid] = accBs;
        redM[tid] = accM;
        __syncthreads();
        for (int off = 128; off > 0; off >>= 1) {
            if (tid < off) { redB[tid] += redB[tid + off]; redM[tid] += redM[tid + off]; }
            __syncthreads();
        }
        if (tid == 0) {
            atomicAdd(&g_acc[3], redB[0]);
            atomicAdd(&g_acc[4], redM[0]);
        }
    }
}

// ---------------------------------------------------------------------------
// Recons SGEMM (FFMA, small): C = Z_last @ F_dec, fused mse vs Xp[:, :, 20]
// ---------------------------------------------------------------------------
__global__ __launch_bounds__(256, 1) void k_recons(
    const float* __restrict__ A, const float* __restrict__ Bm,
    const float* __restrict__ Xp)
{
    __shared__ float As[8][128];
    __shared__ float Bsh[8][128];
    const int tid = threadIdx.x;
    const int tx = tid & 15, ty = tid >> 4;
    const int m0 = blockIdx.x * 128, n0 = blockIdx.y * 128;

    float acc[8][8];
#pragma unroll
    for (int i = 0; i < 8; i++)
#pragma unroll
        for (int j = 0; j < 8; j++) acc[i][j] = 0.f;

    const int arow = tid >> 1, acol = (tid & 1) << 2;
    const int brow = tid >> 5, bcol = (tid & 31) << 2;
    const float* Aptr = A + (size_t)(m0 + arow) * HDIM + acol;
    const float* Bptr = Bm + (size_t)brow * DDIM + n0 + bcol;

    float4 av = *(const float4*)(Aptr);
    float4 bv = *(const float4*)(Bptr);

    for (int k0 = 0; k0 < HDIM; k0 += 8) {
        As[acol + 0][arow] = av.x;
        As[acol + 1][arow] = av.y;
        As[acol + 2][arow] = av.z;
        As[acol + 3][arow] = av.w;
        *(float4*)&Bsh[brow][bcol] = bv;
        __syncthreads();
        if (k0 + 8 < HDIM) {
            av = *(const float4*)(Aptr + k0 + 8);
            bv = *(const float4*)(Bptr + (size_t)(k0 + 8) * DDIM);
        }
#pragma unroll
        for (int kk = 0; kk < 8; kk++) {
            float a[8], b[8];
            *(float4*)(a)     = *(const float4*)&As[kk][ty * 8];
            *(float4*)(a + 4) = *(const float4*)&As[kk][ty * 8 + 4];
            *(float4*)(b)     = *(const float4*)&Bsh[kk][tx * 8];
            *(float4*)(b + 4) = *(const float4*)&Bsh[kk][tx * 8 + 4];
#pragma unroll
            for (int i = 0; i < 8; i++)
#pragma unroll
                for (int j = 0; j < 8; j++) acc[i][j] += a[i] * b[j];
        }
        __syncthreads();
    }

    double ssum = 0.0;
#pragma unroll
    for (int i = 0; i < 8; i++) {
        int m = m0 + ty * 8 + i;
#pragma unroll
        for (int j = 0; j < 8; j++) {
            int n = n0 + tx * 8 + j;
            float x = Xp[(size_t)m * DDIM * TT + (size_t)n * TT + (TT - 1)];
            float diff = acc[i][j] - x;
            ssum += (double)diff * (double)diff;
        }
    }
    __shared__ double red[256];
    red[tid] = ssum;
    __syncthreads();
    for (int off = 128; off > 0; off >>= 1) {
        if (tid < off) red[tid] += red[tid + off];
        __syncthreads();
    }
    if (tid == 0) atomicAdd(&g_acc[0], red[0]);
}

// ---------------------------------------------------------------------------
// Per-row top-100 by |Zt| (binary search on float bit pattern) + Zt losses.
// ---------------------------------------------------------------------------
__global__ __launch_bounds__(256, 1) void k_topk_losses() {
    __shared__ unsigned sabs[HDIM];
    __shared__ int scnt[256];
    __shared__ double sred[256];
    const int b = blockIdx.x;
    const int tid = threadIdx.x;
    const float* zrow = g_Zt + (size_t)b * HDIM;
    const float* zlrow = g_Zp + (size_t)TAUV * BSZ * HDIM + (size_t)b * HDIM;

    for (int h = tid; h < HDIM; h += 256)
        sabs[h] = __float_as_uint(fabsf(zrow[h]));
    __syncthreads();

    unsigned lo = 0u, hi = 0x7f800000u;
    while (lo < hi) {
        unsigned mid = lo + (hi - lo + 1) / 2;
        int c = 0;
        for (int h = tid; h < HDIM; h += 256) c += (sabs[h] >= mid) ? 1 : 0;
        scnt[tid] = c;
        __syncthreads();
        for (int off = 128; off > 0; off >>= 1) {
            if (tid < off) scnt[tid] += scnt[tid + off];
            __syncthreads();
        }
        int cnt = scnt[0];
        __syncthreads();
        if (cnt >= TOPKV) lo = mid; else hi = mid - 1;
    }
    const unsigned thr = lo;

    double s1 = 0.0, s2 = 0.0, s3 = 0.0;
    for (int h = tid; h < HDIM; h += 256) {
        float z = zrow[h];
        float zl = zlrow[h];
        float zm = (sabs[h] >= thr) ? z : 0.f;
        float d1 = zm - zl;
        s1 += (double)d1 * (double)d1;
        s2 += fabs((double)zl - (double)zm);
        s3 += fabs((double)zm);
    }
    sred[tid] = s1;
    __syncthreads();
    for (int off = 128; off > 0; off >>= 1) {
        if (tid < off) sred[tid] += sred[tid + off];
        __syncthreads();
    }
    if (tid == 0) atomicAdd(&g_acc[1], sred[0]);
    __syncthreads();
    sred[tid] = s2;
    __syncthreads();
    for (int off = 128; off > 0; off >>= 1) {
        if (tid < off) sred[tid] += sred[tid + off];
        __syncthreads();
    }
    if (tid == 0) atomicAdd(&g_acc[2], sred[0]);
    __syncthreads();
    sred[tid] = s3;
    __syncthreads();
    for (int off = 128; off > 0; off >>= 1) {
        if (tid < off) sred[tid] += sred[tid + off];
        __syncthreads();
    }
    if (tid == 0) atomicAdd(&g_acc[5], sred[0]);
}

__global__ void k_finalize(float* out) {
    if (threadIdx.x == 0) {
        out[0] = (float)(g_acc[0] / ((double)BSZ * DDIM));
        out[1] = (float)(g_acc[1] / ((double)BSZ * HDIM));
        out[2] = (float)(g_acc[2] / ((double)BSZ * HDIM));
        out[3] = (float)(g_acc[3] / ((double)HDIM * HDIM));
        out[4] = (float)(g_acc[4] / ((double)HDIM * HDIM));
        out[5] = (float)(g_acc[5] / ((double)BSZ * HDIM));
    }
}

extern "C" void kernel_launch(void* const* d_in, const int* in_sizes, int n_in,
                              void* d_out, int out_size) {
    const float* Xp    = (const float*)d_in[0];  // (512,1024,21)
    const float* F_enc = (const float*)d_in[1];  // (1024,4096)
    const float* F_dec = (const float*)d_in[2];  // (4096,1024)
    const float* Bs    = (const float*)d_in[3];  // (20,4096,4096)
    const float* Mm    = (const float*)d_in[4];  // (4096,4096)
    float* out = (float*)d_out;

    // idempotent; not a stream op — capture-safe
    cudaFuncSetAttribute(k_gemm1_hmma, cudaFuncAttributeMaxDynamicSharedMemorySize, SMEM_DYN_BYTES);
    cudaFuncSetAttribute(k_gemm2_hmma, cudaFuncAttributeMaxDynamicSharedMemorySize, SMEM_DYN_BYTES);

    void* pZp = nullptr;
    cudaGetSymbolAddress(&pZp, g_Zp);
    const float* Zlast_ptr = (const float*)pZp + (size_t)TAUV * BSZ * HDIM;

    k_zero_acc<<<1, 32>>>();

    {
        const int total = BSZ * DDIM * TT;
        k_transpose<<<(total + 255) / 256, 256>>>(Xp);
    }
    k_transpose_fenc<<<dim3(DDIM / 32, HDIM / 32), dim3(32, 8)>>>(F_enc);

    // GEMM1 (HMMA): Zp
    k_gemm1_hmma<<<dim3(84, 32), 256, SMEM_DYN_BYTES>>>();

    // Big GEMM (HMMA) + fused |Bs|, |tril(M,1)|
    k_gemm2_hmma<<<dim3(4, 32), 256, SMEM_DYN_BYTES>>>(Bs, Mm);

    // recons + loss_mse_Xt (FFMA, small)
    k_recons<<<dim3(4, 8), 256>>>(Zlast_ptr, F_dec, Xp);

    k_topk_losses<<<BSZ, 256>>>();

    k_finalize<<<1, 32>>>(out);
}

// round 16
// speedup vs baseline: 1.9864x; 1.0789x over previous
#include <cuda_runtime.h>
#include <cuda_bf16.h>
#include <math.h>
#include <stdint.h>

#define BSZ 512
#define DDIM 1024
#define HDIM 4096
#define TAUV 20
#define TT 21
#define TOPKV 100

#define ROWB 80  // smem row pitch bytes: 32 bf16 (64B) + 16B pad -> ldmatrix conflict-free
#define STAGE_BYTES (4 * 128 * ROWB)          // A_hi, A_lo, B_hi, B_lo  = 40960
#define SMEM_DYN_BYTES (2 * STAGE_BYTES)      // 81920
#define GTHREADS 512

// -------- scratch (device globals; no allocation allowed) --------
__device__ float g_Xt[(size_t)BSZ * TT * DDIM];        // [b][t][d]
__device__ float g_Fet[(size_t)HDIM * DDIM];           // F_enc^T [h][d]
__device__ float g_Zp[(size_t)TT * BSZ * HDIM];        // [t][b][h]
__device__ float g_Zt[(size_t)BSZ * HDIM];             // [b][h]
__device__ double g_acc[8];
// acc slots: 0=mseXt 1=mseZt 2=indep 3=absBs 4=absM 5=absZt

// ======================= helpers =======================
__device__ __forceinline__ uint32_t smem_u32(const void* p) {
    uint32_t a;
    asm("{ .reg .u64 t; cvta.to.shared.u64 t, %1; cvt.u32.u64 %0, t; }" : "=r"(a) : "l"(p));
    return a;
}
__device__ __forceinline__ void ldsm_x4(uint32_t* r, uint32_t addr) {
    asm volatile("ldmatrix.sync.aligned.m8n8.x4.shared.b16 {%0,%1,%2,%3}, [%4];"
                 : "=r"(r[0]), "=r"(r[1]), "=r"(r[2]), "=r"(r[3]) : "r"(addr));
}
__device__ __forceinline__ void mma16816(float* c, const uint32_t* a, uint32_t b0, uint32_t b1) {
    asm volatile(
        "mma.sync.aligned.m16n8k16.row.col.f32.bf16.bf16.f32 "
        "{%0,%1,%2,%3}, {%4,%5,%6,%7}, {%8,%9}, {%0,%1,%2,%3};"
        : "+f"(c[0]), "+f"(c[1]), "+f"(c[2]), "+f"(c[3])
        : "r"(a[0]), "r"(a[1]), "r"(a[2]), "r"(a[3]), "r"(b0), "r"(b1));
}

// float4 -> bf16 hi (8B) + bf16 lo residual (8B) at flat smem offset
__device__ __forceinline__ void store_hi_lo(char* th, char* tl, uint32_t off, float4 v) {
    __nv_bfloat16 h0 = __float2bfloat16(v.x);
    __nv_bfloat16 h1 = __float2bfloat16(v.y);
    __nv_bfloat16 h2 = __float2bfloat16(v.z);
    __nv_bfloat16 h3 = __float2bfloat16(v.w);
    __nv_bfloat16 l0 = __float2bfloat16(v.x - __bfloat162float(h0));
    __nv_bfloat16 l1 = __float2bfloat16(v.y - __bfloat162float(h1));
    __nv_bfloat16 l2 = __float2bfloat16(v.z - __bfloat162float(h2));
    __nv_bfloat16 l3 = __float2bfloat16(v.w - __bfloat162float(h3));
    uint2 hv, lv;
    hv.x = ((uint32_t)__bfloat16_as_ushort(h1) << 16) | __bfloat16_as_ushort(h0);
    hv.y = ((uint32_t)__bfloat16_as_ushort(h3) << 16) | __bfloat16_as_ushort(h2);
    lv.x = ((uint32_t)__bfloat16_as_ushort(l1) << 16) | __bfloat16_as_ushort(l0);
    lv.y = ((uint32_t)__bfloat16_as_ushort(l3) << 16) | __bfloat16_as_ushort(l2);
    *(uint2*)(th + off) = hv;
    *(uint2*)(tl + off) = lv;
}

// one Kc=32 chunk, 3-term HMMA, warp tile 32x32; acc[2][4][4]
__device__ __forceinline__ void compute_chunk(float acc[2][4][4],
                                              uint32_t sAh, uint32_t sAl,
                                              uint32_t sBh, uint32_t sBl,
                                              int lane, int wm, int wn) {
#pragma unroll
    for (int ks = 0; ks < 2; ks++) {
        const uint32_t k0b = ks * 32;  // 16 elems = 32 bytes
        uint32_t aoff = (uint32_t)(wm * 32 + (lane & 15)) * ROWB + k0b + ((lane >> 4) & 1) * 16;
        uint32_t aH[2][4], aL[2][4];
        ldsm_x4(aH[0], sAh + aoff);
        ldsm_x4(aH[1], sAh + aoff + 16 * ROWB);
        ldsm_x4(aL[0], sAl + aoff);
        ldsm_x4(aL[1], sAl + aoff + 16 * ROWB);
        uint32_t bH[2][4], bL[2][4];
        uint32_t boff = (uint32_t)(wn * 32 + 8 * ((lane >> 4) & 1) + (lane & 7)) * ROWB
                      + k0b + 16 * ((lane >> 3) & 1);
#pragma unroll
        for (int np = 0; np < 2; np++) {
            ldsm_x4(bH[np], sBh + boff + np * 16 * ROWB);
            ldsm_x4(bL[np], sBl + boff + np * 16 * ROWB);
        }
#pragma unroll
        for (int mt = 0; mt < 2; mt++)
#pragma unroll
            for (int np = 0; np < 2; np++)
#pragma unroll
                for (int sub = 0; sub < 2; sub++) {
                    float* c = acc[mt][np * 2 + sub];
                    mma16816(c, aH[mt], bH[np][sub * 2], bH[np][sub * 2 + 1]);
                    mma16816(c, aH[mt], bL[np][sub * 2], bL[np][sub * 2 + 1]);
                    mma16816(c, aL[mt], bH[np][sub * 2], bH[np][sub * 2 + 1]);
                }
    }
}

__global__ void k_zero_acc() {
    if (threadIdx.x < 8) g_acc[threadIdx.x] = 0.0;
}

// Xp (b,d,t) -> g_Xt (b,t,d)
__global__ void k_transpose(const float* __restrict__ Xp) {
    int idx = blockIdx.x * blockDim.x + threadIdx.x;
    const int total = BSZ * DDIM * TT;
    if (idx >= total) return;
    int b = idx / (DDIM * TT);
    int r = idx - b * (DDIM * TT);
    int d = r / TT;
    int t = r - d * TT;
    g_Xt[(size_t)b * TT * DDIM + (size_t)t * DDIM + d] = Xp[idx];
}

// F_enc (d,h) -> g_Fet (h,d)
__global__ void k_transpose_fenc(const float* __restrict__ Fe) {
    __shared__ float tile[32][33];
    int d0 = blockIdx.x * 32, h0 = blockIdx.y * 32;
    int tx = threadIdx.x, ty = threadIdx.y;
    for (int r = ty; r < 32; r += 8)
        tile[r][tx] = Fe[(size_t)(d0 + r) * HDIM + h0 + tx];
    __syncthreads();
    for (int r = ty; r < 32; r += 8)
        g_Fet[(size_t)(h0 + r) * DDIM + d0 + tx] = tile[tx][r];
}

// ---------------------------------------------------------------------------
// HMMA GEMM1: Zp[(b,t), h] = Xt[(b,t), :] . Fet[h, :]  (K = 1024)
// grid (84, 32), 512 threads (16 warps; warp tile 32x32), Kc=32, 2-stage
// ---------------------------------------------------------------------------
__global__ __launch_bounds__(GTHREADS, 1) void k_gemm1_hmma() {
    extern __shared__ char dsm[];
    const uint32_t sbase = smem_u32(dsm);
    const int tid = threadIdx.x;
    const int lane = tid & 31, w = tid >> 5;
    const int wm = w & 3, wn = w >> 2;
    const int m0 = blockIdx.x * 128, n0 = blockIdx.y * 128;

    float acc[2][4][4];
#pragma unroll
    for (int a = 0; a < 2; a++)
#pragma unroll
        for (int b = 0; b < 4; b++)
#pragma unroll
            for (int c = 0; c < 4; c++) acc[a][b][c] = 0.f;

    const int NIT = DDIM / 32;  // 32
    float4 pa[2], pb[2];
#pragma unroll
    for (int j = 0; j < 2; j++) {
        int fid = tid + j * GTHREADS, row = fid >> 3, c4 = fid & 7;
        pa[j] = *(const float4*)(g_Xt + (size_t)(m0 + row) * DDIM + c4 * 4);
        pb[j] = *(const float4*)(g_Fet + (size_t)(n0 + row) * DDIM + c4 * 4);
    }

    for (int i = 0; i < NIT; i++) {
        const int s = i & 1;
        char* st = dsm + s * STAGE_BYTES;
        char* sAh = st;
        char* sAl = st + 10240;
        char* sBh = st + 20480;
        char* sBl = st + 30720;
#pragma unroll
        for (int j = 0; j < 2; j++) {
            int fid = tid + j * GTHREADS, row = fid >> 3, c4 = fid & 7;
            store_hi_lo(sAh, sAl, row * ROWB + c4 * 8, pa[j]);
            store_hi_lo(sBh, sBl, row * ROWB + c4 * 8, pb[j]);
        }
        __syncthreads();
        if (i + 1 < NIT) {
            int kg = (i + 1) * 32;
#pragma unroll
            for (int j = 0; j < 2; j++) {
                int fid = tid + j * GTHREADS, row = fid >> 3, c4 = fid & 7;
                pa[j] = *(const float4*)(g_Xt + (size_t)(m0 + row) * DDIM + kg + c4 * 4);
                pb[j] = *(const float4*)(g_Fet + (size_t)(n0 + row) * DDIM + kg + c4 * 4);
            }
        }
        uint32_t u = sbase + s * STAGE_BYTES;
        compute_chunk(acc, u, u + 10240, u + 20480, u + 30720, lane, wm, wn);
        __syncthreads();
    }

    // epilogue: scatter m=(b*21+t) rows into g_Zp[t][b][h]
#pragma unroll
    for (int mt = 0; mt < 2; mt++) {
        int r0 = m0 + wm * 32 + mt * 16 + (lane >> 2);
        int b0i = r0 / TT, t0i = r0 - b0i * TT;
        int r1 = r0 + 8;
        int b1i = r1 / TT, t1i = r1 - b1i * TT;
        float* d0p = g_Zp + (size_t)t0i * BSZ * HDIM + (size_t)b0i * HDIM;
        float* d1p = g_Zp + (size_t)t1i * BSZ * HDIM + (size_t)b1i * HDIM;
#pragma unroll
        for (int nt = 0; nt < 4; nt++) {
            int col = n0 + wn * 32 + nt * 8 + (lane & 3) * 2;
            *(float2*)(d0p + col) = make_float2(acc[mt][nt][0], acc[mt][nt][1]);
            *(float2*)(d1p + col) = make_float2(acc[mt][nt][2], acc[mt][nt][3]);
        }
    }
}

// ---------------------------------------------------------------------------
// HMMA big GEMM: Zt[b,h] = sum_{l<20} Bs[l,h,:].Zp[19-l][b,:] + tril(M,1)[h,:].Zp[20][b,:]
// grid (4, 32), 512 threads. Fused |Bs| / |tril M| sums on blockIdx.x==0.
// ---------------------------------------------------------------------------
__global__ __launch_bounds__(GTHREADS, 1) void k_gemm2_hmma(
    const float* __restrict__ Bs, const float* __restrict__ Mmat)
{
    extern __shared__ char dsm[];
    const uint32_t sbase = smem_u32(dsm);
    const int tid = threadIdx.x;
    const int lane = tid & 31, w = tid >> 5;
    const int wm = w & 3, wn = w >> 2;
    const int m0 = blockIdx.x * 128, n0 = blockIdx.y * 128;
    const bool doAbs = (blockIdx.x == 0);
    double accBs = 0.0, accM = 0.0;

    float acc[2][4][4];
#pragma unroll
    for (int a = 0; a < 2; a++)
#pragma unroll
        for (int b = 0; b < 4; b++)
#pragma unroll
            for (int c = 0; c < 4; c++) acc[a][b][c] = 0.f;

    const int CPS = HDIM / 32;          // 128 chunks per l-slab
    const int NIT = (TAUV + 1) * CPS;   // 2688

    float4 pa[2], pb[2];
    {   // prefetch chunk 0 (l=0 -> tsel=19, Wbase=Bs[0])
        const float* Abase = g_Zp + (size_t)(TAUV - 1) * BSZ * HDIM;
        const float* Wbase = Bs;
#pragma unroll
        for (int j = 0; j < 2; j++) {
            int fid = tid + j * GTHREADS, row = fid >> 3, c4 = fid & 7;
            pa[j] = *(const float4*)(Abase + (size_t)(m0 + row) * HDIM + c4 * 4);
            pb[j] = *(const float4*)(Wbase + (size_t)(n0 + row) * HDIM + c4 * 4);
        }
    }

    for (int i = 0; i < NIT; i++) {
        const int s = i & 1;
        const int l = i >> 7;               // i / 128
        const int kglob = (i & 127) << 5;   // (i % 128) * 32
        char* st = dsm + s * STAGE_BYTES;
        char* sAh = st;
        char* sAl = st + 10240;
        char* sBh = st + 20480;
        char* sBl = st + 30720;
#pragma unroll
        for (int j = 0; j < 2; j++) {
            int fid = tid + j * GTHREADS, row = fid >> 3, c4 = fid & 7;
            store_hi_lo(sAh, sAl, row * ROWB + c4 * 8, pa[j]);
            float4 wv = pb[j];
            int h = n0 + row;
            int d0 = kglob + c4 * 4;
            if (l == TAUV) {  // tril(M, k=1): keep d <= h+1
                if (d0 + 0 > h + 1) wv.x = 0.f;
                if (d0 + 1 > h + 1) wv.y = 0.f;
                if (d0 + 2 > h + 1) wv.z = 0.f;
                if (d0 + 3 > h + 1) wv.w = 0.f;
            }
            if (doAbs) {
                float sab = fabsf(wv.x) + fabsf(wv.y) + fabsf(wv.z) + fabsf(wv.w);
                if (l < TAUV) accBs += (double)sab; else accM += (double)sab;
            }
            store_hi_lo(sBh, sBl, row * ROWB + c4 * 8, wv);
        }
        __syncthreads();
        if (i + 1 < NIT) {
            int ci = i + 1;
            int ln = ci >> 7;
            int kg = (ci & 127) << 5;
            int tsel = (ln < TAUV) ? (TAUV - 1 - ln) : TAUV;
            const float* Abase = g_Zp + (size_t)tsel * BSZ * HDIM;
            const float* Wbase = (ln < TAUV) ? (Bs + (size_t)ln * HDIM * HDIM) : Mmat;
#pragma unroll
            for (int j = 0; j < 2; j++) {
                int fid = tid + j * GTHREADS, row = fid >> 3, c4 = fid & 7;
                pa[j] = *(const float4*)(Abase + (size_t)(m0 + row) * HDIM + kg + c4 * 4);
                pb[j] = *(const float4*)(Wbase + (size_t)(n0 + row) * HDIM + kg + c4 * 4);
            }
        }
        uint32_t u = sbase + s * STAGE_BYTES;
        compute_chunk(acc, u, u + 10240, u + 20480, u + 30720, lane, wm, wn);
        __syncthreads();
    }

    // epilogue: Zt[b][h]
#pragma unroll
    for (int mt = 0; mt < 2; mt++) {
        int r0 = m0 + wm * 32 + mt * 16 + (lane >> 2);
#pragma unroll
        for (int nt = 0; nt < 4; nt++) {
            int col = n0 + wn * 32 + nt * 8 + (lane & 3) * 2;
            *(float2*)(g_Zt + (size_t)r0 * HDIM + col) = make_float2(acc[mt][nt][0], acc[mt][nt][1]);
            *(float2*)(g_Zt + (size_t)(r0 + 8) * HDIM + col) = make_float2(acc[mt][nt][2], acc[mt][nt][3]);
        }
    }

    if (doAbs) {
        __shared__ double redB[GTHREADS];
        __shared__ double redM[GTHREADS];
        redB[tid] = accBs;
        redM[tid] = accM;
        __syncthreads();
        for (int off = GTHREADS / 2; off > 0; off >>= 1) {
            if (tid < off) { redB[tid] += redB[tid + off]; redM[tid] += redM[tid + off]; }
            __syncthreads();
        }
        if (tid == 0) {
            atomicAdd(&g_acc[3], redB[0]);
            atomicAdd(&g_acc[4], redM[0]);
        }
    }
}

// ---------------------------------------------------------------------------
// Recons SGEMM (FFMA, 64x64 tiles, grid (8,16)=128 CTAs): C = Z_last @ F_dec,
// fused mse vs Xp[:, :, 20]. As padded to 68 floats/row (272B = 17*16) so the
// float4 reads stay 16B-aligned (65-pad was the R15 misaligned-address bug).
// ---------------------------------------------------------------------------
__global__ __launch_bounds__(256, 1) void k_recons(
    const float* __restrict__ A, const float* __restrict__ Bm,
    const float* __restrict__ Xp)
{
    __shared__ float As[16][68];
    __shared__ float Bsh[16][64];
    const int tid = threadIdx.x;
    const int tx = tid & 15, ty = tid >> 4;
    const int m0 = blockIdx.x * 64, n0 = blockIdx.y * 64;

    float acc[4][4];
#pragma unroll
    for (int i = 0; i < 4; i++)
#pragma unroll
        for (int j = 0; j < 4; j++) acc[i][j] = 0.f;

    const int arow = tid >> 2, ac4 = tid & 3;      // A: 64 rows x 16 k (4 float4)
    const int brow = tid >> 4, bc4 = tid & 15;     // B: 16 rows x 64 n (16 float4)
    const float* Aptr = A + (size_t)(m0 + arow) * HDIM + ac4 * 4;
    const float* Bptr = Bm + (size_t)brow * DDIM + n0 + bc4 * 4;

    float4 av = *(const float4*)(Aptr);
    float4 bv = *(const float4*)(Bptr);

    for (int k0 = 0; k0 < HDIM; k0 += 16) {
        As[ac4 * 4 + 0][arow] = av.x;
        As[ac4 * 4 + 1][arow] = av.y;
        As[ac4 * 4 + 2][arow] = av.z;
        As[ac4 * 4 + 3][arow] = av.w;
        *(float4*)&Bsh[brow][bc4 * 4] = bv;
        __syncthreads();
        if (k0 + 16 < HDIM) {
            av = *(const float4*)(Aptr + k0 + 16);
            bv = *(const float4*)(Bptr + (size_t)(k0 + 16) * DDIM);
        }
#pragma unroll
        for (int kk = 0; kk < 16; kk++) {
            float a[4], b[4];
            *(float4*)(a) = *(const float4*)&As[kk][ty * 4];
            *(float4*)(b) = *(const float4*)&Bsh[kk][tx * 4];
#pragma unroll
            for (int i = 0; i < 4; i++)
#pragma unroll
                for (int j = 0; j < 4; j++) acc[i][j] += a[i] * b[j];
        }
        __syncthreads();
    }

    double ssum = 0.0;
#pragma unroll
    for (int i = 0; i < 4; i++) {
        int m = m0 + ty * 4 + i;
#pragma unroll
        for (int j = 0; j < 4; j++) {
            int n = n0 + tx * 4 + j;
            float x = Xp[(size_t)m * DDIM * TT + (size_t)n * TT + (TT - 1)];
            float diff = acc[i][j] - x;
            ssum += (double)diff * (double)diff;
        }
    }
    __shared__ double red[256];
    red[tid] = ssum;
    __syncthreads();
    for (int off = 128; off > 0; off >>= 1) {
        if (tid < off) red[tid] += red[tid + off];
        __syncthreads();
    }
    if (tid == 0) atomicAdd(&g_acc[0], red[0]);
}

// ---------------------------------------------------------------------------
// Per-row top-100 by |Zt| (binary search on float bit pattern) + Zt losses.
// ---------------------------------------------------------------------------
__global__ __launch_bounds__(256, 1) void k_topk_losses() {
    __shared__ unsigned sabs[HDIM];
    __shared__ int scnt[256];
    __shared__ double sred[256];
    const int b = blockIdx.x;
    const int tid = threadIdx.x;
    const float* zrow = g_Zt + (size_t)b * HDIM;
    const float* zlrow = g_Zp + (size_t)TAUV * BSZ * HDIM + (size_t)b * HDIM;

    for (int h = tid; h < HDIM; h += 256)
        sabs[h] = __float_as_uint(fabsf(zrow[h]));
    __syncthreads();

    unsigned lo = 0u, hi = 0x7f800000u;
    while (lo < hi) {
        unsigned mid = lo + (hi - lo + 1) / 2;
        int c = 0;
        for (int h = tid; h < HDIM; h += 256) c += (sabs[h] >= mid) ? 1 : 0;
        scnt[tid] = c;
        __syncthreads();
        for (int off = 128; off > 0; off >>= 1) {
            if (tid < off) scnt[tid] += scnt[tid + off];
            __syncthreads();
        }
        int cnt = scnt[0];
        __syncthreads();
        if (cnt >= TOPKV) lo = mid; else hi = mid - 1;
    }
    const unsigned thr = lo;

    double s1 = 0.0, s2 = 0.0, s3 = 0.0;
    for (int h = tid; h < HDIM; h += 256) {
        float z = zrow[h];
        float zl = zlrow[h];
        float zm = (sabs[h] >= thr) ? z : 0.f;
        float d1 = zm - zl;
        s1 += (double)d1 * (double)d1;
        s2 += fabs((double)zl - (double)zm);
        s3 += fabs((double)zm);
    }
    sred[tid] = s1;
    __syncthreads();
    for (int off = 128; off > 0; off >>= 1) {
        if (tid < off) sred[tid] += sred[tid + off];
        __syncthreads();
    }
    if (tid == 0) atomicAdd(&g_acc[1], sred[0]);
    __syncthreads();
    sred[tid] = s2;
    __syncthreads();
    for (int off = 128; off > 0; off >>= 1) {
        if (tid < off) sred[tid] += sred[tid + off];
        __syncthreads();
    }
    if (tid == 0) atomicAdd(&g_acc[2], sred[0]);
    __syncthreads();
    sred[tid] = s3;
    __syncthreads();
    for (int off = 128; off > 0; off >>= 1) {
        if (tid < off) sred[tid] += sred[tid + off];
        __syncthreads();
    }
    if (tid == 0) atomicAdd(&g_acc[5], sred[0]);
}

__global__ void k_finalize(float* out) {
    if (threadIdx.x == 0) {
        out[0] = (float)(g_acc[0] / ((double)BSZ * DDIM));
        out[1] = (float)(g_acc[1] / ((double)BSZ * HDIM));
        out[2] = (float)(g_acc[2] / ((double)BSZ * HDIM));
        out[3] = (float)(g_acc[3] / ((double)HDIM * HDIM));
        out[4] = (float)(g_acc[4] / ((double)HDIM * HDIM));
        out[5] = (float)(g_acc[5] / ((double)BSZ * HDIM));
    }
}

extern "C" void kernel_launch(void* const* d_in, const int* in_sizes, int n_in,
                              void* d_out, int out_size) {
    const float* Xp    = (const float*)d_in[0];  // (512,1024,21)
    const float* F_enc = (const float*)d_in[1];  // (1024,4096)
    const float* F_dec = (const float*)d_in[2];  // (4096,1024)
    const float* Bs    = (const float*)d_in[3];  // (20,4096,4096)
    const float* Mm    = (const float*)d_in[4];  // (4096,4096)
    float* out = (float*)d_out;

    // idempotent; not a stream op — capture-safe
    cudaFuncSetAttribute(k_gemm1_hmma, cudaFuncAttributeMaxDynamicSharedMemorySize, SMEM_DYN_BYTES);
    cudaFuncSetAttribute(k_gemm2_hmma, cudaFuncAttributeMaxDynamicSharedMemorySize, SMEM_DYN_BYTES);

    void* pZp = nullptr;
    cudaGetSymbolAddress(&pZp, g_Zp);
    const float* Zlast_ptr = (const float*)pZp + (size_t)TAUV * BSZ * HDIM;

    k_zero_acc<<<1, 32>>>();

    {
        const int total = BSZ * DDIM * TT;
        k_transpose<<<(total + 255) / 256, 256>>>(Xp);
    }
    k_transpose_fenc<<<dim3(DDIM / 32, HDIM / 32), dim3(32, 8)>>>(F_enc);

    // GEMM1 (HMMA, 16 warps): Zp
    k_gemm1_hmma<<<dim3(84, 32), GTHREADS, SMEM_DYN_BYTES>>>();

    // Big GEMM (HMMA, 16 warps) + fused |Bs|, |tril(M,1)|
    k_gemm2_hmma<<<dim3(4, 32), GTHREADS, SMEM_DYN_BYTES>>>(Bs, Mm);

    // recons + loss_mse_Xt (FFMA, 128 CTAs)
    k_recons<<<dim3(8, 16), 256>>>(Zlast_ptr, F_dec, Xp);

    k_topk_losses<<<BSZ, 256>>>();

    k_finalize<<<1, 32>>>(out);
}